// round 16
// baseline (speedup 1.0000x reference)
#include <cuda_runtime.h>
#include <cuda_fp16.h>
#include <stdint.h>

#define N_NODES 50000
#define N_EDGES 600000
#define D 128
#define M_PAD 50048               // 391 * 128
#define N_TILES 391
#define GRID_GEMM 148
#define CNT_PAD 53248             // 1024 * 52

#define PITCH 136                 // halves per smem tile row (272B = 68 banks)
#define TILE_H (128 * PITCH)      // halves per tile (34816 B)

// ---------------- scratch (no allocations allowed) ----------------
__device__ __align__(16) int    g_count[CNT_PAD];
__device__ int    g_rowptr[N_NODES + 1];
__device__ int    g_cursor[N_NODES];
__device__ int    g_esrc[N_EDGES];
__device__ float  g_deginv[N_NODES];
__device__ __align__(16) float  g_hA[M_PAD * D];     // layer-1 out fp32 (agg input)
__device__ __align__(16) float  g_hB[M_PAD * D];     // layer-2 out fp32 (agg input)
__device__ __align__(16) __half g_phiA[M_PAD * D];   // activation hi (pair A)
__device__ __align__(16) __half g_ploA[M_PAD * D];   // activation lo (pair A)
__device__ __align__(16) __half g_phiB[M_PAD * D];   // pair B
__device__ __align__(16) __half g_ploB[M_PAD * D];
__device__ __align__(16) __half g_phiN[M_PAD * D];   // neighbor-agg pair
__device__ __align__(16) __half g_ploN[M_PAD * D];
__device__ __align__(16) __half g_whi[6 * D * D];    // Whi[n][k] (transposed, hi)
__device__ __align__(16) __half g_wlo[6 * D * D];    // Wlo[n][k] (transposed, lo)

// ================= CSR build =================
__global__ void k_zero_counts() {
    int i = blockIdx.x * blockDim.x + threadIdx.x;
    if (i < CNT_PAD) g_count[i] = 0;
}

__global__ void k_hist(const int* __restrict__ dst) {
    int e = blockIdx.x * blockDim.x + threadIdx.x;
    if (e < N_EDGES) atomicAdd(&g_count[dst[e]], 1);
}

__global__ void k_scan() {
    __shared__ int sums[1024];
    int t = threadIdx.x;
    const int4* cp = (const int4*)g_count;
    int base4 = t * 13;
    int s = 0;
#pragma unroll
    for (int i = 0; i < 13; i++) {
        int4 v = cp[base4 + i];
        s += v.x + v.y + v.z + v.w;
    }
    sums[t] = s;
    __syncthreads();
    for (int off = 1; off < 1024; off <<= 1) {
        int v = (t >= off) ? sums[t - off] : 0;
        __syncthreads();
        sums[t] += v;
        __syncthreads();
    }
    int run = (t == 0) ? 0 : sums[t - 1];
    int beg = t * 52;
#pragma unroll
    for (int i = 0; i < 13; i++) {
        int4 v = cp[base4 + i];
        int vals[4] = {v.x, v.y, v.z, v.w};
#pragma unroll
        for (int j = 0; j < 4; j++) {
            int idx = beg + i * 4 + j;
            if (idx < N_NODES) {
                g_rowptr[idx] = run;
                g_cursor[idx] = run;
                g_deginv[idx] = 1.0f / fmaxf((float)vals[j], 1.0f);
            }
            run += vals[j];
        }
    }
    if (t == 1023) g_rowptr[N_NODES] = run;
}

__global__ void k_scatter(const int* __restrict__ src, const int* __restrict__ dst) {
    int e = blockIdx.x * blockDim.x + threadIdx.x;
    if (e < N_EDGES) {
        int p = atomicAdd(&g_cursor[dst[e]], 1);
        g_esrc[p] = src[e];
    }
}

// ====== weight transpose + fp16 hi/lo split (6 matrices, one launch) ======
struct WtArgs { const float* w[6]; };

__global__ void k_wt(WtArgs args) {
    __shared__ float tile[32][33];
    const float* W = args.w[blockIdx.z];
    __half* Whi = g_whi + blockIdx.z * D * D;
    __half* Wlo = g_wlo + blockIdx.z * D * D;
    int bx = blockIdx.x * 32, by = blockIdx.y * 32;   // bx: n-range, by: k-range
#pragma unroll
    for (int j = 0; j < 32; j += 8)
        tile[threadIdx.y + j][threadIdx.x] = W[(by + threadIdx.y + j) * D + bx + threadIdx.x];
    __syncthreads();
#pragma unroll
    for (int j = 0; j < 32; j += 8) {
        float x = tile[threadIdx.x][threadIdx.y + j];   // W[k=by+tx][n=bx+ty+j]
        __half h = __float2half_rn(x);
        __half l = __float2half_rn(x - __half2float(h));
        int n = bx + threadIdx.y + j, k = by + threadIdx.x;
        Whi[n * D + k] = h;
        Wlo[n * D + k] = l;
    }
}

// ====== fp32 -> fp16 hi/lo split of a full activation matrix (padded) ======
__device__ __forceinline__ void split4(float4 v, uint2* uh, uint2* ul) {
    __half h0 = __float2half_rn(v.x), h1 = __float2half_rn(v.y);
    __half h2 = __float2half_rn(v.z), h3 = __float2half_rn(v.w);
    __half l0 = __float2half_rn(v.x - __half2float(h0));
    __half l1 = __float2half_rn(v.y - __half2float(h1));
    __half l2 = __float2half_rn(v.z - __half2float(h2));
    __half l3 = __float2half_rn(v.w - __half2float(h3));
    __half2 a = __halves2half2(h0, h1), b = __halves2half2(h2, h3);
    __half2 c = __halves2half2(l0, l1), d = __halves2half2(l2, l3);
    uh->x = *(uint32_t*)&a; uh->y = *(uint32_t*)&b;
    ul->x = *(uint32_t*)&c; ul->y = *(uint32_t*)&d;
}

__global__ void k_split(const float* __restrict__ src, __half* __restrict__ hi,
                        __half* __restrict__ lo) {
    int i = blockIdx.x * blockDim.x + threadIdx.x;   // float4 index
    if (i >= M_PAD * D / 4) return;
    int row = i >> 5;                                 // 32 float4 per row
    float4 v = make_float4(0.f, 0.f, 0.f, 0.f);
    if (row < N_NODES) v = *(const float4*)(src + (size_t)i * 4);
    uint2 uh, ul;
    split4(v, &uh, &ul);
    *(uint2*)(hi + (size_t)i * 4) = uh;
    *(uint2*)(lo + (size_t)i * 4) = ul;
}

// ====== neighbor aggregation: gathers fp32, writes fp16 hi/lo pair ======
__global__ void k_agg(const float* __restrict__ h, __half* __restrict__ outHi,
                      __half* __restrict__ outLo) {
    int node = (blockIdx.x * blockDim.x + threadIdx.x) >> 5;
    int lane = threadIdx.x & 31;
    if (node >= N_NODES) return;
    int beg = g_rowptr[node];
    int end = g_rowptr[node + 1];
    float4 acc0 = make_float4(0.f, 0.f, 0.f, 0.f);
    float4 acc1 = make_float4(0.f, 0.f, 0.f, 0.f);
    int e = beg;
    for (; e + 1 < end; e += 2) {
        int s0 = g_esrc[e];
        int s1 = g_esrc[e + 1];
        float4 v0 = ((const float4*)(h + (size_t)s0 * D))[lane];
        float4 v1 = ((const float4*)(h + (size_t)s1 * D))[lane];
        acc0.x += v0.x; acc0.y += v0.y; acc0.z += v0.z; acc0.w += v0.w;
        acc1.x += v1.x; acc1.y += v1.y; acc1.z += v1.z; acc1.w += v1.w;
    }
    if (e < end) {
        int s0 = g_esrc[e];
        float4 v0 = ((const float4*)(h + (size_t)s0 * D))[lane];
        acc0.x += v0.x; acc0.y += v0.y; acc0.z += v0.z; acc0.w += v0.w;
    }
    float di = g_deginv[node];
    float4 r;
    r.x = (acc0.x + acc1.x) * di;
    r.y = (acc0.y + acc1.y) * di;
    r.z = (acc0.z + acc1.z) * di;
    r.w = (acc0.w + acc1.w) * di;
    uint2 uh, ul;
    split4(r, &uh, &ul);
    size_t off = (size_t)node * D + lane * 4;
    *(uint2*)(outHi + off) = uh;
    *(uint2*)(outLo + off) = ul;
}

// ================= HMMA split-fp16 dual GEMM (persistent) =================
// out = A0*W0 + A1*W1 + bias (+relu); A supplied pre-split as fp16 hi/lo.
// Per product: Ahi*Whi + Alo*Whi + Ahi*Wlo (lo*lo dropped, ~2^-22 relative).
// Epilogue writes fp32 out (next agg) and optionally hi/lo pair (next GEMM A0).
#define SM_AHI 0
#define SM_ALO (1 * TILE_H)
#define SM_W0H (2 * TILE_H)
#define SM_W0L (3 * TILE_H)
#define SM_W1H (4 * TILE_H)
#define SM_W1L (5 * TILE_H)
#define SM_BIAS_BYTES (6 * TILE_H * 2)
#define SMEM_BYTES (SM_BIAS_BYTES + 512 + 128)

// pure fp16 copy of one 128x128 tile pair into pitched smem
__device__ __forceinline__ void fill_A16(const __half* __restrict__ hiSrc,
                                         const __half* __restrict__ loSrc,
                                         int rowBase, __half* Ahi, __half* Alo,
                                         int tid) {
    for (int i = tid; i < 2048; i += 256) {       // 2048 uint4 per matrix
        int r = i >> 4;                            // row 0..127
        int k = (i & 15) << 3;                     // 0..120 step 8
        size_t goff = (size_t)(rowBase + r) * D + k;
        uint4 vh = *(const uint4*)(hiSrc + goff);
        *(uint4*)&Ahi[r * PITCH + k] = vh;
        uint4 vl = *(const uint4*)(loSrc + goff);
        *(uint4*)&Alo[r * PITCH + k] = vl;
    }
}

// stage a 128x128 fp16 weight (row-major [n][k]) into pitched smem
__device__ __forceinline__ void fill_W(const __half* __restrict__ src, __half* dst,
                                       int tid) {
    for (int i = tid; i < 2048; i += 256) {
        int n = i >> 4;
        int k = (i & 15) << 3;
        uint4 v = *(const uint4*)(src + n * D + k);
        *(uint4*)&dst[n * PITCH + k] = v;
    }
}

// one K=128 MMA pass
__device__ __forceinline__ void mma_pass(const __half* At, const __half* Wt,
                                         float acc[2][8][4], int mbase, int nbase,
                                         int g, int q) {
#pragma unroll
    for (int k0 = 0; k0 < 128; k0 += 16) {
        uint32_t a[2][4];
#pragma unroll
        for (int mf = 0; mf < 2; mf++) {
            const __half* ar = At + (mbase + mf * 16 + g) * PITCH + k0 + q * 2;
            a[mf][0] = *(const uint32_t*)(ar);                 // row,   k lo
            a[mf][1] = *(const uint32_t*)(ar + 8 * PITCH);     // row+8, k lo
            a[mf][2] = *(const uint32_t*)(ar + 8);             // row,   k hi
            a[mf][3] = *(const uint32_t*)(ar + 8 * PITCH + 8); // row+8, k hi
        }
#pragma unroll
        for (int nf = 0; nf < 8; nf++) {
            const __half* br = Wt + (nbase + nf * 8 + g) * PITCH + k0 + q * 2;
            uint32_t b0 = *(const uint32_t*)(br);
            uint32_t b1 = *(const uint32_t*)(br + 8);
#pragma unroll
            for (int mf = 0; mf < 2; mf++) {
                asm volatile(
                    "mma.sync.aligned.m16n8k16.row.col.f32.f16.f16.f32 "
                    "{%0,%1,%2,%3}, {%4,%5,%6,%7}, {%8,%9}, {%0,%1,%2,%3};"
                    : "+f"(acc[mf][nf][0]), "+f"(acc[mf][nf][1]),
                      "+f"(acc[mf][nf][2]), "+f"(acc[mf][nf][3])
                    : "r"(a[mf][0]), "r"(a[mf][1]), "r"(a[mf][2]), "r"(a[mf][3]),
                      "r"(b0), "r"(b1));
            }
        }
    }
}

__device__ __forceinline__ void store_split2(__half* hi, __half* lo, size_t off,
                                             float o0, float o1) {
    __half h0 = __float2half_rn(o0), h1 = __float2half_rn(o1);
    __half l0 = __float2half_rn(o0 - __half2float(h0));
    __half l1 = __float2half_rn(o1 - __half2float(h1));
    __half2 ph = __halves2half2(h0, h1);
    __half2 pl = __halves2half2(l0, l1);
    *(__half2*)(hi + off) = ph;
    *(__half2*)(lo + off) = pl;
}

__global__ __launch_bounds__(256, 1) void k_gemm_mma(
    const __half* __restrict__ A0hi, const __half* __restrict__ A0lo,
    const __half* __restrict__ A1hi, const __half* __restrict__ A1lo,
    const __half* __restrict__ W0hi, const __half* __restrict__ W0lo,
    const __half* __restrict__ W1hi, const __half* __restrict__ W1lo,
    const float* __restrict__ bias, float* __restrict__ out,
    __half* __restrict__ outHi, __half* __restrict__ outLo,
    int relu, int guardOut, int writeSplit)
{
    extern __shared__ __half sm[];
    __half* Ahi = sm + SM_AHI;
    __half* Alo = sm + SM_ALO;
    __half* W0h = sm + SM_W0H;
    __half* W0l = sm + SM_W0L;
    __half* W1h = sm + SM_W1H;
    __half* W1l = sm + SM_W1L;
    float* bS = (float*)((char*)sm + SM_BIAS_BYTES);

    int tid = threadIdx.x;
    int wid = tid >> 5;
    int lane = tid & 31;
    int g = lane >> 2;        // groupID 0..7
    int q = lane & 3;         // quad 0..3
    int mbase = (wid & 3) * 32;
    int nbase = (wid >> 2) * 64;

    // stage resident weights + bias
    fill_W(W0hi, W0h, tid);
    fill_W(W0lo, W0l, tid);
    fill_W(W1hi, W1h, tid);
    fill_W(W1lo, W1l, tid);
    if (tid < D) bS[tid] = bias[tid];

    float acc[2][8][4];
#pragma unroll
    for (int mf = 0; mf < 2; mf++)
#pragma unroll
        for (int nf = 0; nf < 8; nf++)
#pragma unroll
            for (int c = 0; c < 4; c++) acc[mf][nf][c] = 0.f;

    for (int t = blockIdx.x; t < N_TILES; t += GRID_GEMM) {
        int rowBase = t * 128;

        __syncthreads();                       // A bufs free (prev readers done)
        fill_A16(A0hi, A0lo, rowBase, Ahi, Alo, tid);
        __syncthreads();
        mma_pass(Ahi, W0h, acc, mbase, nbase, g, q);
        mma_pass(Alo, W0h, acc, mbase, nbase, g, q);
        mma_pass(Ahi, W0l, acc, mbase, nbase, g, q);

        __syncthreads();                       // done reading A (self)
        fill_A16(A1hi, A1lo, rowBase, Ahi, Alo, tid);
        __syncthreads();
        mma_pass(Ahi, W1h, acc, mbase, nbase, g, q);
        mma_pass(Alo, W1h, acc, mbase, nbase, g, q);
        mma_pass(Ahi, W1l, acc, mbase, nbase, g, q);

        // epilogue: bias, relu, store fp32 (+ optional hi/lo split), zero acc
#pragma unroll
        for (int mf = 0; mf < 2; mf++) {
#pragma unroll
            for (int nf = 0; nf < 8; nf++) {
                int col = nbase + nf * 8 + q * 2;
                float b0 = bS[col], b1 = bS[col + 1];
                float o0 = acc[mf][nf][0] + b0;
                float o1 = acc[mf][nf][1] + b1;
                float o2 = acc[mf][nf][2] + b0;
                float o3 = acc[mf][nf][3] + b1;
                if (relu) {
                    o0 = fmaxf(o0, 0.f); o1 = fmaxf(o1, 0.f);
                    o2 = fmaxf(o2, 0.f); o3 = fmaxf(o3, 0.f);
                }
                int r0 = rowBase + mbase + mf * 16 + g;
                int r1 = r0 + 8;
                if (!guardOut || r0 < N_NODES) {
                    size_t off = (size_t)r0 * D + col;
                    *(float2*)(out + off) = make_float2(o0, o1);
                    if (writeSplit) store_split2(outHi, outLo, off, o0, o1);
                }
                if (!guardOut || r1 < N_NODES) {
                    size_t off = (size_t)r1 * D + col;
                    *(float2*)(out + off) = make_float2(o2, o3);
                    if (writeSplit) store_split2(outHi, outLo, off, o2, o3);
                }
                acc[mf][nf][0] = 0.f; acc[mf][nf][1] = 0.f;
                acc[mf][nf][2] = 0.f; acc[mf][nf][3] = 0.f;
            }
        }
    }
}

// ================= launch =================
extern "C" void kernel_launch(void* const* d_in, const int* in_sizes, int n_in,
                              void* d_out, int out_size) {
    const float* g_features = (const float*)d_in[0];
    const int*   src        = (const int*)d_in[1];
    const int*   dst        = (const int*)d_in[2];
    const float* W_self1    = (const float*)d_in[3];
    const float* W_neigh1   = (const float*)d_in[4];
    const float* b1         = (const float*)d_in[5];
    const float* W_self2    = (const float*)d_in[6];
    const float* W_neigh2   = (const float*)d_in[7];
    const float* b2         = (const float*)d_in[8];
    const float* W_self3    = (const float*)d_in[9];
    const float* W_neigh3   = (const float*)d_in[10];
    const float* b3         = (const float*)d_in[11];
    float* out = (float*)d_out;

    float *hA, *hB;
    __half *whi, *wlo, *phiA, *ploA, *phiB, *ploB, *phiN, *ploN;
    cudaGetSymbolAddress((void**)&hA, g_hA);
    cudaGetSymbolAddress((void**)&hB, g_hB);
    cudaGetSymbolAddress((void**)&whi, g_whi);
    cudaGetSymbolAddress((void**)&wlo, g_wlo);
    cudaGetSymbolAddress((void**)&phiA, g_phiA);
    cudaGetSymbolAddress((void**)&ploA, g_ploA);
    cudaGetSymbolAddress((void**)&phiB, g_phiB);
    cudaGetSymbolAddress((void**)&ploB, g_ploB);
    cudaGetSymbolAddress((void**)&phiN, g_phiN);
    cudaGetSymbolAddress((void**)&ploN, g_ploN);

    cudaFuncSetAttribute(k_gemm_mma, cudaFuncAttributeMaxDynamicSharedMemorySize,
                         SMEM_BYTES);

    const int TB = 256;
    int cntBlocks   = (CNT_PAD + TB - 1) / TB;
    int edgeBlocks  = (N_EDGES + TB - 1) / TB;
    int aggBlocks   = (N_NODES * 32 + TB - 1) / TB;
    int splitBlocks = (M_PAD * D / 4 + TB - 1) / TB;

    // CSR build (reused by all 3 layers)
    k_zero_counts<<<cntBlocks, TB>>>();
    k_hist<<<edgeBlocks, TB>>>(dst);
    k_scan<<<1, 1024>>>();
    k_scatter<<<edgeBlocks, TB>>>(src, dst);

    // transpose + split all 6 weight matrices
    WtArgs wa;
    wa.w[0] = W_self1; wa.w[1] = W_neigh1;
    wa.w[2] = W_self2; wa.w[3] = W_neigh2;
    wa.w[4] = W_self3; wa.w[5] = W_neigh3;
    k_wt<<<dim3(4, 4, 6), dim3(32, 8)>>>(wa);

    // split input features into pair A (padded rows zeroed)
    k_split<<<splitBlocks, TB>>>(g_features, phiA, ploA);

    // layer 1: agg(g_features) -> pairN ; gemm -> hA fp32 + pairB
    k_agg<<<aggBlocks, TB>>>(g_features, phiN, ploN);
    k_gemm_mma<<<GRID_GEMM, 256, SMEM_BYTES>>>(
        phiA, ploA, phiN, ploN,
        whi + 0 * D * D, wlo + 0 * D * D, whi + 1 * D * D, wlo + 1 * D * D,
        b1, hA, phiB, ploB, 1, 0, 1);
    // layer 2: agg(hA) -> pairN ; gemm(pairB, pairN) -> hB fp32 + pairA
    k_agg<<<aggBlocks, TB>>>(hA, phiN, ploN);
    k_gemm_mma<<<GRID_GEMM, 256, SMEM_BYTES>>>(
        phiB, ploB, phiN, ploN,
        whi + 2 * D * D, wlo + 2 * D * D, whi + 3 * D * D, wlo + 3 * D * D,
        b2, hB, phiA, ploA, 1, 0, 1);
    // layer 3: agg(hB) -> pairN ; gemm(pairA, pairN) -> d_out fp32 (guarded)
    k_agg<<<aggBlocks, TB>>>(hB, phiN, ploN);
    k_gemm_mma<<<GRID_GEMM, 256, SMEM_BYTES>>>(
        phiA, ploA, phiN, ploN,
        whi + 4 * D * D, wlo + 4 * D * D, whi + 5 * D * D, wlo + 5 * D * D,
        b3, out, ((__half*)0), ((__half*)0), 0, 1, 0);
}

// round 17
// speedup vs baseline: 1.0808x; 1.0808x over previous
#include <cuda_runtime.h>
#include <cuda_fp16.h>
#include <stdint.h>

#define N_NODES 50000
#define N_EDGES 600000
#define D 128
#define M_PAD 50048               // 391 * 128
#define N_TILES 391
#define GRID_GEMM 148
#define CNT_PAD 53248             // 1024 * 52

#define PITCH 136                 // halves per smem tile row (272B = 68 banks)
#define TILE_H (128 * PITCH)      // halves per tile (34816 B)

// ---------------- scratch (no allocations allowed) ----------------
__device__ __align__(16) int    g_count[CNT_PAD];
__device__ int    g_rowptr[N_NODES + 1];
__device__ int    g_cursor[N_NODES];
__device__ int    g_esrc[N_EDGES];
__device__ float  g_deginv[N_NODES];
__device__ __align__(16) float  g_hn[M_PAD * D];     // agg output (padded, zero-init)
__device__ __align__(16) float  g_hA[M_PAD * D];
__device__ __align__(16) float  g_hB[M_PAD * D];
__device__ __align__(16) __half g_whi[6 * D * D];    // Whi[n][k] (transposed, hi)
__device__ __align__(16) __half g_wlo[6 * D * D];    // Wlo[n][k] (transposed, lo)

// ================= CSR build =================
__global__ void k_zero_counts() {
    int i = blockIdx.x * blockDim.x + threadIdx.x;
    if (i < CNT_PAD) g_count[i] = 0;
}

__global__ void k_hist(const int* __restrict__ dst) {
    int e = blockIdx.x * blockDim.x + threadIdx.x;
    if (e < N_EDGES) atomicAdd(&g_count[dst[e]], 1);
}

__global__ void k_scan() {
    __shared__ int sums[1024];
    int t = threadIdx.x;
    const int4* cp = (const int4*)g_count;
    int base4 = t * 13;
    int s = 0;
#pragma unroll
    for (int i = 0; i < 13; i++) {
        int4 v = cp[base4 + i];
        s += v.x + v.y + v.z + v.w;
    }
    sums[t] = s;
    __syncthreads();
    for (int off = 1; off < 1024; off <<= 1) {
        int v = (t >= off) ? sums[t - off] : 0;
        __syncthreads();
        sums[t] += v;
        __syncthreads();
    }
    int run = (t == 0) ? 0 : sums[t - 1];
    int beg = t * 52;
#pragma unroll
    for (int i = 0; i < 13; i++) {
        int4 v = cp[base4 + i];
        int vals[4] = {v.x, v.y, v.z, v.w};
#pragma unroll
        for (int j = 0; j < 4; j++) {
            int idx = beg + i * 4 + j;
            if (idx < N_NODES) {
                g_rowptr[idx] = run;
                g_cursor[idx] = run;
                g_deginv[idx] = 1.0f / fmaxf((float)vals[j], 1.0f);
            }
            run += vals[j];
        }
    }
    if (t == 1023) g_rowptr[N_NODES] = run;
}

__global__ void k_scatter(const int* __restrict__ src, const int* __restrict__ dst) {
    int e = blockIdx.x * blockDim.x + threadIdx.x;
    if (e < N_EDGES) {
        int p = atomicAdd(&g_cursor[dst[e]], 1);
        g_esrc[p] = src[e];
    }
}

// ====== weight transpose + fp16 hi/lo split (6 matrices, one launch) ======
struct WtArgs { const float* w[6]; };

__global__ void k_wt(WtArgs args) {
    __shared__ float tile[32][33];
    const float* W = args.w[blockIdx.z];
    __half* Whi = g_whi + blockIdx.z * D * D;
    __half* Wlo = g_wlo + blockIdx.z * D * D;
    int bx = blockIdx.x * 32, by = blockIdx.y * 32;   // bx: n-range, by: k-range
#pragma unroll
    for (int j = 0; j < 32; j += 8)
        tile[threadIdx.y + j][threadIdx.x] = W[(by + threadIdx.y + j) * D + bx + threadIdx.x];
    __syncthreads();
#pragma unroll
    for (int j = 0; j < 32; j += 8) {
        float x = tile[threadIdx.x][threadIdx.y + j];   // W[k=by+tx][n=bx+ty+j]
        __half h = __float2half_rn(x);
        __half l = __float2half_rn(x - __half2float(h));
        int n = bx + threadIdx.y + j, k = by + threadIdx.x;
        Whi[n * D + k] = h;
        Wlo[n * D + k] = l;
    }
}

// ================= neighbor aggregation (R14: fp32 out) =================
__global__ void k_agg(const float* __restrict__ h, float* __restrict__ out) {
    int node = (blockIdx.x * blockDim.x + threadIdx.x) >> 5;
    int lane = threadIdx.x & 31;
    if (node >= N_NODES) return;
    int beg = g_rowptr[node];
    int end = g_rowptr[node + 1];
    float4 acc0 = make_float4(0.f, 0.f, 0.f, 0.f);
    float4 acc1 = make_float4(0.f, 0.f, 0.f, 0.f);
    int e = beg;
    for (; e + 1 < end; e += 2) {
        int s0 = g_esrc[e];
        int s1 = g_esrc[e + 1];
        float4 v0 = ((const float4*)(h + (size_t)s0 * D))[lane];
        float4 v1 = ((const float4*)(h + (size_t)s1 * D))[lane];
        acc0.x += v0.x; acc0.y += v0.y; acc0.z += v0.z; acc0.w += v0.w;
        acc1.x += v1.x; acc1.y += v1.y; acc1.z += v1.z; acc1.w += v1.w;
    }
    if (e < end) {
        int s0 = g_esrc[e];
        float4 v0 = ((const float4*)(h + (size_t)s0 * D))[lane];
        acc0.x += v0.x; acc0.y += v0.y; acc0.z += v0.z; acc0.w += v0.w;
    }
    float di = g_deginv[node];
    float4 r;
    r.x = (acc0.x + acc1.x) * di;
    r.y = (acc0.y + acc1.y) * di;
    r.z = (acc0.z + acc1.z) * di;
    r.w = (acc0.w + acc1.w) * di;
    ((float4*)(out + (size_t)node * D))[lane] = r;
}

// ================= HMMA split-fp16 dual GEMM (persistent) =================
// out = A0*W0 + A1*W1 + bias (+relu); per product 3-term fp16 split.
// A fills: register-prefetch (LDG issued one phase early, hidden behind MMA),
// then cvt+STS between barriers.
#define SM_AHI 0
#define SM_ALO (1 * TILE_H)
#define SM_W0H (2 * TILE_H)
#define SM_W0L (3 * TILE_H)
#define SM_W1H (4 * TILE_H)
#define SM_W1L (5 * TILE_H)
#define SM_BIAS_BYTES (6 * TILE_H * 2)
#define SMEM_BYTES (SM_BIAS_BYTES + 512 + 128)

__device__ __forceinline__ uint32_t pack2(__half a, __half b) {
    __half2 p = __halves2half2(a, b);
    return *(uint32_t*)&p;
}

// issue this thread's 16 float4 A-loads into registers (guarded, zero default)
__device__ __forceinline__ void pref_load(const float* __restrict__ src, int rowBase,
                                          int tid, int guard, float4 pref[16]) {
#pragma unroll
    for (int j = 0; j < 16; j++) {
        int i = tid + j * 256;        // 0..4095
        int r = i >> 5;               // row 0..127
        int c4 = (i & 31) << 2;       // col 0..124 step 4
        int row = rowBase + r;
        float4 v = make_float4(0.f, 0.f, 0.f, 0.f);
        if (!guard || row < N_NODES)
            v = *(const float4*)(src + (size_t)row * D + c4);
        pref[j] = v;
    }
}

// split prefetched registers into Ahi/Alo smem (pitched), same mapping
__device__ __forceinline__ void pref_store(const float4 pref[16], __half* Ahi,
                                           __half* Alo, int tid) {
#pragma unroll
    for (int j = 0; j < 16; j++) {
        int i = tid + j * 256;
        int r = i >> 5;
        int c4 = (i & 31) << 2;
        float4 v = pref[j];
        __half h0 = __float2half_rn(v.x), h1 = __float2half_rn(v.y);
        __half h2 = __float2half_rn(v.z), h3 = __float2half_rn(v.w);
        __half l0 = __float2half_rn(v.x - __half2float(h0));
        __half l1 = __float2half_rn(v.y - __half2float(h1));
        __half l2 = __float2half_rn(v.z - __half2float(h2));
        __half l3 = __float2half_rn(v.w - __half2float(h3));
        uint2 uh; uh.x = pack2(h0, h1); uh.y = pack2(h2, h3);
        uint2 ul; ul.x = pack2(l0, l1); ul.y = pack2(l2, l3);
        *(uint2*)&Ahi[r * PITCH + c4] = uh;
        *(uint2*)&Alo[r * PITCH + c4] = ul;
    }
}

// stage a 128x128 fp16 weight (row-major [n][k]) into pitched smem
__device__ __forceinline__ void fill_W(const __half* __restrict__ src, __half* dst,
                                       int tid) {
    for (int i = tid; i < 2048; i += 256) {
        int n = i >> 4;
        int k = (i & 15) << 3;
        uint4 v = *(const uint4*)(src + n * D + k);
        *(uint4*)&dst[n * PITCH + k] = v;
    }
}

// one K=128 MMA pass
__device__ __forceinline__ void mma_pass(const __half* At, const __half* Wt,
                                         float acc[2][8][4], int mbase, int nbase,
                                         int g, int q) {
#pragma unroll
    for (int k0 = 0; k0 < 128; k0 += 16) {
        uint32_t a[2][4];
#pragma unroll
        for (int mf = 0; mf < 2; mf++) {
            const __half* ar = At + (mbase + mf * 16 + g) * PITCH + k0 + q * 2;
            a[mf][0] = *(const uint32_t*)(ar);                 // row,   k lo
            a[mf][1] = *(const uint32_t*)(ar + 8 * PITCH);     // row+8, k lo
            a[mf][2] = *(const uint32_t*)(ar + 8);             // row,   k hi
            a[mf][3] = *(const uint32_t*)(ar + 8 * PITCH + 8); // row+8, k hi
        }
#pragma unroll
        for (int nf = 0; nf < 8; nf++) {
            const __half* br = Wt + (nbase + nf * 8 + g) * PITCH + k0 + q * 2;
            uint32_t b0 = *(const uint32_t*)(br);
            uint32_t b1 = *(const uint32_t*)(br + 8);
#pragma unroll
            for (int mf = 0; mf < 2; mf++) {
                asm volatile(
                    "mma.sync.aligned.m16n8k16.row.col.f32.f16.f16.f32 "
                    "{%0,%1,%2,%3}, {%4,%5,%6,%7}, {%8,%9}, {%0,%1,%2,%3};"
                    : "+f"(acc[mf][nf][0]), "+f"(acc[mf][nf][1]),
                      "+f"(acc[mf][nf][2]), "+f"(acc[mf][nf][3])
                    : "r"(a[mf][0]), "r"(a[mf][1]), "r"(a[mf][2]), "r"(a[mf][3]),
                      "r"(b0), "r"(b1));
            }
        }
    }
}

__global__ __launch_bounds__(256, 1) void k_gemm_mma(
    const float* __restrict__ A0, const float* __restrict__ A1,
    const __half* __restrict__ W0hi, const __half* __restrict__ W0lo,
    const __half* __restrict__ W1hi, const __half* __restrict__ W1lo,
    const float* __restrict__ bias, float* __restrict__ out,
    int relu, int guardA, int guardOut)
{
    extern __shared__ __half sm[];
    __half* Ahi = sm + SM_AHI;
    __half* Alo = sm + SM_ALO;
    __half* W0h = sm + SM_W0H;
    __half* W0l = sm + SM_W0L;
    __half* W1h = sm + SM_W1H;
    __half* W1l = sm + SM_W1L;
    float* bS = (float*)((char*)sm + SM_BIAS_BYTES);

    int tid = threadIdx.x;
    int wid = tid >> 5;
    int lane = tid & 31;
    int g = lane >> 2;        // groupID 0..7
    int q = lane & 3;         // quad 0..3
    int mbase = (wid & 3) * 32;
    int nbase = (wid >> 2) * 64;

    // stage resident weights + bias
    fill_W(W0hi, W0h, tid);
    fill_W(W0lo, W0l, tid);
    fill_W(W1hi, W1h, tid);
    fill_W(W1lo, W1l, tid);
    if (tid < D) bS[tid] = bias[tid];

    float acc[2][8][4];
#pragma unroll
    for (int mf = 0; mf < 2; mf++)
#pragma unroll
        for (int nf = 0; nf < 8; nf++)
#pragma unroll
            for (int c = 0; c < 4; c++) acc[mf][nf][c] = 0.f;

    float4 pref[16];
    pref_load(A0, blockIdx.x * 128, tid, guardA, pref);   // prologue: first A0

    for (int t = blockIdx.x; t < N_TILES; t += GRID_GEMM) {
        int rowBase = t * 128;
        int tn = t + GRID_GEMM;

        __syncthreads();                        // A bufs free (prev readers done)
        pref_store(pref, Ahi, Alo, tid);        // A0 -> smem
        pref_load(A1, rowBase, tid, 0, pref);   // issue A1 loads (hidden by MMA)
        __syncthreads();
        mma_pass(Ahi, W0h, acc, mbase, nbase, g, q);
        mma_pass(Alo, W0h, acc, mbase, nbase, g, q);
        mma_pass(Ahi, W0l, acc, mbase, nbase, g, q);

        __syncthreads();                        // done reading A0 smem
        pref_store(pref, Ahi, Alo, tid);        // A1 -> smem
        if (tn < N_TILES)
            pref_load(A0, tn * 128, tid, guardA, pref);  // next tile's A0
        __syncthreads();
        mma_pass(Ahi, W1h, acc, mbase, nbase, g, q);
        mma_pass(Alo, W1h, acc, mbase, nbase, g, q);
        mma_pass(Ahi, W1l, acc, mbase, nbase, g, q);

        // epilogue: bias, relu, store, zero acc (overlaps next A0 loads)
#pragma unroll
        for (int mf = 0; mf < 2; mf++) {
#pragma unroll
            for (int nf = 0; nf < 8; nf++) {
                int col = nbase + nf * 8 + q * 2;
                float b0 = bS[col], b1 = bS[col + 1];
                float o0 = acc[mf][nf][0] + b0;
                float o1 = acc[mf][nf][1] + b1;
                float o2 = acc[mf][nf][2] + b0;
                float o3 = acc[mf][nf][3] + b1;
                if (relu) {
                    o0 = fmaxf(o0, 0.f); o1 = fmaxf(o1, 0.f);
                    o2 = fmaxf(o2, 0.f); o3 = fmaxf(o3, 0.f);
                }
                int r0 = rowBase + mbase + mf * 16 + g;
                int r1 = r0 + 8;
                if (!guardOut || r0 < N_NODES)
                    *(float2*)(out + (size_t)r0 * D + col) = make_float2(o0, o1);
                if (!guardOut || r1 < N_NODES)
                    *(float2*)(out + (size_t)r1 * D + col) = make_float2(o2, o3);
                acc[mf][nf][0] = 0.f; acc[mf][nf][1] = 0.f;
                acc[mf][nf][2] = 0.f; acc[mf][nf][3] = 0.f;
            }
        }
    }
}

// ================= launch =================
extern "C" void kernel_launch(void* const* d_in, const int* in_sizes, int n_in,
                              void* d_out, int out_size) {
    const float* g_features = (const float*)d_in[0];
    const int*   src        = (const int*)d_in[1];
    const int*   dst        = (const int*)d_in[2];
    const float* W_self1    = (const float*)d_in[3];
    const float* W_neigh1   = (const float*)d_in[4];
    const float* b1         = (const float*)d_in[5];
    const float* W_self2    = (const float*)d_in[6];
    const float* W_neigh2   = (const float*)d_in[7];
    const float* b2         = (const float*)d_in[8];
    const float* W_self3    = (const float*)d_in[9];
    const float* W_neigh3   = (const float*)d_in[10];
    const float* b3         = (const float*)d_in[11];
    float* out = (float*)d_out;

    float *hn, *hA, *hB;
    __half *whi, *wlo;
    cudaGetSymbolAddress((void**)&hn, g_hn);
    cudaGetSymbolAddress((void**)&hA, g_hA);
    cudaGetSymbolAddress((void**)&hB, g_hB);
    cudaGetSymbolAddress((void**)&whi, g_whi);
    cudaGetSymbolAddress((void**)&wlo, g_wlo);

    cudaFuncSetAttribute(k_gemm_mma, cudaFuncAttributeMaxDynamicSharedMemorySize,
                         SMEM_BYTES);

    const int TB = 256;
    int cntBlocks  = (CNT_PAD + TB - 1) / TB;
    int edgeBlocks = (N_EDGES + TB - 1) / TB;
    int aggBlocks  = (N_NODES * 32 + TB - 1) / TB;

    // CSR build (reused by all 3 layers)
    k_zero_counts<<<cntBlocks, TB>>>();
    k_hist<<<edgeBlocks, TB>>>(dst);
    k_scan<<<1, 1024>>>();
    k_scatter<<<edgeBlocks, TB>>>(src, dst);

    // transpose + split all 6 weight matrices
    WtArgs wa;
    wa.w[0] = W_self1; wa.w[1] = W_neigh1;
    wa.w[2] = W_self2; wa.w[3] = W_neigh2;
    wa.w[4] = W_self3; wa.w[5] = W_neigh3;
    k_wt<<<dim3(4, 4, 6), dim3(32, 8)>>>(wa);

    // layer 1 (A0 = harness input: guard loads; out = padded scratch)
    k_agg<<<aggBlocks, TB>>>(g_features, hn);
    k_gemm_mma<<<GRID_GEMM, 256, SMEM_BYTES>>>(
        g_features, hn, whi + 0 * D * D, wlo + 0 * D * D,
        whi + 1 * D * D, wlo + 1 * D * D, b1, hA, 1, 1, 0);
    // layer 2
    k_agg<<<aggBlocks, TB>>>(hA, hn);
    k_gemm_mma<<<GRID_GEMM, 256, SMEM_BYTES>>>(
        hA, hn, whi + 2 * D * D, wlo + 2 * D * D,
        whi + 3 * D * D, wlo + 3 * D * D, b2, hB, 1, 0, 0);
    // layer 3 (out = d_out: guard stores)
    k_agg<<<aggBlocks, TB>>>(hB, hn);
    k_gemm_mma<<<GRID_GEMM, 256, SMEM_BYTES>>>(
        hB, hn, whi + 4 * D * D, wlo + 4 * D * D,
        whi + 5 * D * D, wlo + 5 * D * D, b3, out, 0, 0, 1);
}